// round 16
// baseline (speedup 1.0000x reference)
#include <cuda_runtime.h>
#include <math.h>

#define BB 4
#define LL 8192
#define DD 2048
#define BLT (BB * LL)          // 32768 rows
#define CAP (LL / 2)           // 4096
#define NOISE_SCALE 0.1f
#define AUX_W 0.01f
#define CAP_F 0.5f

#define TPB  256
#define NBLK (BLT / 8)         // 4096 matvec blocks, 1 row/warp
#define BPB  (NBLK / BB)       // 1024 matvec blocks per batch
#define SEPT (LL / TPB)        // 32 keys per thread in select

// Scratch (allocations forbidden). All state is self-resetting per replay.
__device__ unsigned g_keys[BLT];          // order-mapped noisy logits
__device__ float    g_part[NBLK];         // per-block sigmoid partials
__device__ unsigned g_hist[BB][256];      // per-batch top-byte histograms
__device__ unsigned g_batch_done[BB] = {0, 0, 0, 0};   // producer counters

__device__ __forceinline__ unsigned atom_add_release_gpu(unsigned* p, unsigned v) {
    unsigned old;
    asm volatile("atom.add.release.gpu.global.u32 %0, [%1], %2;"
                 : "=r"(old) : "l"(p), "r"(v) : "memory");
    return old;
}
__device__ __forceinline__ unsigned ld_acquire_gpu(const unsigned* p) {
    unsigned v;
    asm volatile("ld.acquire.gpu.global.u32 %0, [%1];"
                 : "=r"(v) : "l"(p) : "memory");
    return v;
}

// ---------------------------------------------------------------------------
// Kernel 1: router matvec (proven shape ~41.5us) + pass-0 histogram +
// per-batch release counter. Fires PDL trigger at each block's end.
// ---------------------------------------------------------------------------
__global__ __launch_bounds__(TPB) void matvec_kernel(
    const float* __restrict__ x,
    const float* __restrict__ noise,
    const float* __restrict__ w,
    float* __restrict__ out)
{
    __shared__ float4 sw[DD / 4];     // 8 KB router weight
    __shared__ float  ssig[8];

    const int t = threadIdx.x;
    const float4* w4 = reinterpret_cast<const float4*>(w);
    sw[t]       = w4[t];
    sw[t + 256] = w4[t + 256];
    __syncthreads();

    const int warp = t >> 5;
    const int lane = t & 31;
    const int row  = blockIdx.x * 8 + warp;

    const float4* xr = reinterpret_cast<const float4*>(x + (size_t)row * DD);
    float acc = 0.0f;
#pragma unroll
    for (int j = 0; j < 16; j++) {
        const float4 xv = __ldg(&xr[lane + 32 * j]);
        const float4 wv = sw[lane + 32 * j];
        acc = fmaf(xv.x, wv.x, acc);
        acc = fmaf(xv.y, wv.y, acc);
        acc = fmaf(xv.z, wv.z, acc);
        acc = fmaf(xv.w, wv.w, acc);
    }
#pragma unroll
    for (int o = 16; o; o >>= 1) acc += __shfl_down_sync(0xffffffffu, acc, o);

    if (lane == 0) {
        out[BLT + row] = acc;                                // clean logit
        const float ny = fmaf(noise[row], NOISE_SCALE, acc); // noisy logit
        const unsigned nb = __float_as_uint(ny);
        const unsigned key = nb ^ (((int)nb >> 31) | 0x80000000u);
        g_keys[row] = key;                                   // monotone map
        atomicAdd(&g_hist[row >> 13][key >> 24], 1u);        // pass-0 bin
        ssig[warp] = 1.0f / (1.0f + expf(-acc));
    }
    __syncthreads();
    if (t == 0) {
        float s = 0.0f;
#pragma unroll
        for (int i = 0; i < 8; i++) s += ssig[i];
        g_part[blockIdx.x] = s;
        // release: all this block's key/logit/hist writes become visible
        // before the counter increment is observed.
        atom_add_release_gpu(&g_batch_done[blockIdx.x / BPB], 1u);
    }
    __syncthreads();
    cudaTriggerProgrammaticLaunchCompletion();
}

// ---------------------------------------------------------------------------
// Kernel 2 (PDL secondary, overlapped): blocks 0..3 spin on their batch's
// producer counter (runs while later batches still stream); block 4 = aux
// (grid-wide PDL sync — needs all g_part).
// ---------------------------------------------------------------------------
__global__ __launch_bounds__(TPB) void select_aux_kernel(float* __restrict__ out)
{
    __shared__ unsigned s_hist[256];
    __shared__ unsigned s_tot[8];
    __shared__ unsigned s_state[2];   // [0]=prefix, [1]=need
    __shared__ unsigned s_cnt;
    __shared__ int      s_eqn;
    __shared__ int      s_eqi[256];
    __shared__ double   s_dbw[8 * BB];

    const int t    = threadIdx.x;
    const int warp = t >> 5;
    const int lane = t & 31;
    const int bid  = blockIdx.x;

    if (bid == BB) {
        // ---------------- aux loss: needs the whole matvec ----------------
        cudaGridDependencySynchronize();
        double v[BB];
#pragma unroll
        for (int bq = 0; bq < BB; bq++) {
            v[bq] = (double)g_part[bq * 1024 + t]
                  + (double)g_part[bq * 1024 + 256 + t]
                  + (double)g_part[bq * 1024 + 512 + t]
                  + (double)g_part[bq * 1024 + 768 + t];
#pragma unroll
            for (int o = 16; o; o >>= 1)
                v[bq] += __shfl_down_sync(0xffffffffu, v[bq], o);
        }
        if (lane == 0)
#pragma unroll
            for (int bq = 0; bq < BB; bq++) s_dbw[warp * BB + bq] = v[bq];
        __syncthreads();
        if (t == 0) {
            double a = 0.0;
#pragma unroll
            for (int bq = 0; bq < BB; bq++) {
                double s = 0.0;
#pragma unroll
                for (int wq = 0; wq < 8; wq++) s += s_dbw[wq * BB + bq];
                const double d = s / (double)LL - (double)CAP_F;
                a += d * d;
            }
            out[2 * BLT] = (float)((double)AUX_W * a / (double)BB);
        }
        return;
    }

    // ---------------- per-row top-CAP select (overlapped start) ----------
    const int srow = bid;
    // wait only for THIS batch's 1024 producer blocks
    if (t == 0) {
        while (ld_acquire_gpu(&g_batch_done[srow]) != (unsigned)BPB)
            __nanosleep(32);
        g_batch_done[srow] = 0u;      // reset for next graph replay
    }
    __syncthreads();

    unsigned k[SEPT];
    {
        const uint4* kr = reinterpret_cast<const uint4*>(g_keys + srow * LL);
#pragma unroll
        for (int q = 0; q < SEPT / 4; q++) {
            const uint4 v = __ldg(&kr[t * (SEPT / 4) + q]);
            k[q * 4 + 0] = v.x; k[q * 4 + 1] = v.y;
            k[q * 4 + 2] = v.z; k[q * 4 + 3] = v.w;
        }
    }

    // ---- pass 0: histogram prebuilt by matvec; read, then zero for replay
    const unsigned h0 = g_hist[srow][t];
    g_hist[srow][t] = 0u;
    if (t == 0) { s_cnt = 0u; s_eqn = 0; }
    {
        unsigned v = h0;
#pragma unroll
        for (int o = 1; o < 32; o <<= 1) {
            const unsigned u = __shfl_down_sync(0xffffffffu, v, o);
            if (lane + o < 32) v += u;
        }
        if (lane == 0) s_tot[warp] = v;
        __syncthreads();
        unsigned carry = 0;
#pragma unroll
        for (int w2 = 0; w2 < 8; w2++) if (w2 > warp) carry += s_tot[w2];
        const unsigned S = v + carry;                 // suffix incl. own bin
        if (h0 > 0u && S >= (unsigned)CAP && (S - h0) < (unsigned)CAP) {
            s_state[0] = (unsigned)t << 24;
            s_state[1] = (unsigned)CAP - (S - h0);
        }
        __syncthreads();
    }

    // ---- passes 1-3: prefix-filtered (few participants) ----
#pragma unroll
    for (int pass = 1; pass < 4; pass++) {
        const int s  = 24 - 8 * pass;
        const int hs = s + 8;
        s_hist[t] = 0u;
        __syncthreads();
        const unsigned prefix = s_state[0];
        const unsigned need   = s_state[1];
#pragma unroll
        for (int j = 0; j < SEPT; j++) {
            if (((k[j] ^ prefix) >> hs) == 0u)
                atomicAdd(&s_hist[(k[j] >> s) & 255u], 1u);
        }
        __syncthreads();
        const unsigned h = s_hist[t];
        unsigned v = h;
#pragma unroll
        for (int o = 1; o < 32; o <<= 1) {
            const unsigned u = __shfl_down_sync(0xffffffffu, v, o);
            if (lane + o < 32) v += u;
        }
        if (lane == 0) s_tot[warp] = v;
        __syncthreads();
        unsigned carry = 0;
#pragma unroll
        for (int w2 = 0; w2 < 8; w2++) if (w2 > warp) carry += s_tot[w2];
        const unsigned S = v + carry;
        if (h > 0u && S >= need && (S - h) < need) {
            s_state[0] = prefix | ((unsigned)t << s);
            s_state[1] = need - (S - h);
        }
        __syncthreads();
    }
    const unsigned thr = s_state[0];                  // exact CAP-th largest

    // mask write + strict-greater count + tie collection (from registers)
    float4* m4 = reinterpret_cast<float4*>(out + srow * LL);
    int cg = 0;
#pragma unroll
    for (int q = 0; q < SEPT / 4; q++) {
        float4 mv;
        mv.x = (k[q * 4 + 0] > thr) ? 1.0f : 0.0f;
        mv.y = (k[q * 4 + 1] > thr) ? 1.0f : 0.0f;
        mv.z = (k[q * 4 + 2] > thr) ? 1.0f : 0.0f;
        mv.w = (k[q * 4 + 3] > thr) ? 1.0f : 0.0f;
        m4[t * (SEPT / 4) + q] = mv;
        cg += (int)mv.x + (int)mv.y + (int)mv.z + (int)mv.w;
#pragma unroll
        for (int c = 0; c < 4; c++) {
            if (k[q * 4 + c] == thr) {
                const int p = atomicAdd(&s_eqn, 1);
                if (p < 256) s_eqi[p] = t * SEPT + q * 4 + c;
            }
        }
    }
    cg = __reduce_add_sync(0xffffffffu, cg);
    if (lane == 0 && cg) atomicAdd(&s_cnt, (unsigned)cg);
    __syncthreads();

    // promote lowest-index ties to fill exactly CAP (jax top_k order)
    if (t == 0) {
        float* m = out + srow * LL;
        int need = CAP - (int)s_cnt;
        const int n = (s_eqn < 256) ? s_eqn : 256;
        for (int sel = 0; sel < need; sel++) {
            int best = 0x7fffffff, bi = -1;
            for (int q = 0; q < n; q++)
                if (s_eqi[q] >= 0 && s_eqi[q] < best) { best = s_eqi[q]; bi = q; }
            if (bi < 0) break;
            m[best]   = 1.0f;
            s_eqi[bi] = -1;
        }
    }
}

// ---------------------------------------------------------------------------
extern "C" void kernel_launch(void* const* d_in, const int* in_sizes, int n_in,
                              void* d_out, int out_size)
{
    const float* x     = (const float*)d_in[0];
    const float* noise = (const float*)d_in[1];
    const float* w     = (const float*)d_in[2];
    float* out = (float*)d_out;   // [mask BL | logits BL | aux 1]
    (void)in_sizes; (void)n_in; (void)out_size;

    matvec_kernel<<<NBLK, TPB>>>(x, noise, w, out);

    // PDL secondary: launches while the matvec drains; per-batch spin waits
    // let select blocks start as soon as their batch's rows are produced.
    cudaLaunchConfig_t cfg = {};
    cfg.gridDim  = dim3(BB + 1, 1, 1);
    cfg.blockDim = dim3(TPB, 1, 1);
    cfg.dynamicSmemBytes = 0;
    cfg.stream = 0;
    cudaLaunchAttribute attrs[1];
    attrs[0].id = cudaLaunchAttributeProgrammaticStreamSerialization;
    attrs[0].val.programmaticStreamSerializationAllowed = 1;
    cfg.attrs = attrs;
    cfg.numAttrs = 1;
    cudaLaunchKernelEx(&cfg, select_aux_kernel, out);
}

// round 17
// speedup vs baseline: 1.0903x; 1.0903x over previous
#include <cuda_runtime.h>
#include <math.h>

#define BB 4
#define LL 8192
#define DD 2048
#define BLT (BB * LL)          // 32768 rows
#define CAP (LL / 2)           // 4096
#define NOISE_SCALE 0.1f
#define AUX_W 0.01f
#define CAP_F 0.5f

#define TPB  256
#define NBLK (BLT / 8)         // 4096 matvec blocks, 1 row/warp
#define SEPT (LL / TPB)        // 32 keys per thread in select

// Scratch (allocations forbidden). g_hist starts zeroed (static init) and is
// re-zeroed by the select kernel after use -> clean state for every replay.
__device__ unsigned g_keys[BLT];        // order-mapped noisy logits
__device__ float    g_part[NBLK];       // per-block sigmoid partials
__device__ unsigned g_hist[BB][256];    // per-batch top-byte histograms

// ---------------------------------------------------------------------------
// Kernel 1: router matvec. Single-use 256MB stream of x -> evict-first
// streaming loads (__ldcs) so L2 doesn't churn allocate/evict on dead lines.
// Also prebuilds the select's pass-0 top-byte histogram.
// ---------------------------------------------------------------------------
__global__ __launch_bounds__(TPB) void matvec_kernel(
    const float* __restrict__ x,
    const float* __restrict__ noise,
    const float* __restrict__ w,
    float* __restrict__ out)
{
    __shared__ float4 sw[DD / 4];     // 8 KB router weight
    __shared__ float  ssig[8];

    const int t = threadIdx.x;
    const float4* w4 = reinterpret_cast<const float4*>(w);
    sw[t]       = w4[t];
    sw[t + 256] = w4[t + 256];
    __syncthreads();

    const int warp = t >> 5;
    const int lane = t & 31;
    const int row  = blockIdx.x * 8 + warp;

    const float4* xr = reinterpret_cast<const float4*>(x + (size_t)row * DD);
    float acc = 0.0f;
#pragma unroll
    for (int j = 0; j < 16; j++) {
        const float4 xv = __ldcs(&xr[lane + 32 * j]);   // evict-first stream
        const float4 wv = sw[lane + 32 * j];
        acc = fmaf(xv.x, wv.x, acc);
        acc = fmaf(xv.y, wv.y, acc);
        acc = fmaf(xv.z, wv.z, acc);
        acc = fmaf(xv.w, wv.w, acc);
    }
#pragma unroll
    for (int o = 16; o; o >>= 1) acc += __shfl_down_sync(0xffffffffu, acc, o);

    if (lane == 0) {
        __stcs(&out[BLT + row], acc);                    // clean logit (stream)
        const float ny = fmaf(noise[row], NOISE_SCALE, acc); // noisy logit
        const unsigned nb = __float_as_uint(ny);
        const unsigned key = nb ^ (((int)nb >> 31) | 0x80000000u);
        g_keys[row] = key;                               // monotone map
        atomicAdd(&g_hist[row >> 13][key >> 24], 1u);    // pass-0 bin
        ssig[warp] = 1.0f / (1.0f + expf(-acc));
    }
    __syncthreads();
    if (t == 0) {
        float s = 0.0f;
#pragma unroll
        for (int i = 0; i < 8; i++) s += ssig[i];
        g_part[blockIdx.x] = s;      // plain store, no init needed
    }
    __syncthreads();
    cudaTriggerProgrammaticLaunchCompletion();
}

// ---------------------------------------------------------------------------
// Kernel 2 (PDL secondary): grid-wide dependency sync, then
// blocks 0..3 = per-row top-CAP select (pass-0 histogram prebuilt);
// block 4 = aux loss.
// ---------------------------------------------------------------------------
__global__ __launch_bounds__(TPB) void select_aux_kernel(float* __restrict__ out)
{
    __shared__ unsigned s_hist[256];
    __shared__ unsigned s_tot[8];
    __shared__ unsigned s_state[2];   // [0]=prefix, [1]=need
    __shared__ unsigned s_cnt;
    __shared__ int      s_eqn;
    __shared__ int      s_eqi[256];
    __shared__ double   s_dbw[8 * BB];

    const int t    = threadIdx.x;
    const int warp = t >> 5;
    const int lane = t & 31;
    const int bid  = blockIdx.x;

    // wait for the matvec's memory to be visible (PDL dependency)
    cudaGridDependencySynchronize();

    if (bid == BB) {
        // ---------------- aux loss ----------------
        double v[BB];
#pragma unroll
        for (int bq = 0; bq < BB; bq++) {
            v[bq] = (double)g_part[bq * 1024 + t]
                  + (double)g_part[bq * 1024 + 256 + t]
                  + (double)g_part[bq * 1024 + 512 + t]
                  + (double)g_part[bq * 1024 + 768 + t];
#pragma unroll
            for (int o = 16; o; o >>= 1)
                v[bq] += __shfl_down_sync(0xffffffffu, v[bq], o);
        }
        if (lane == 0)
#pragma unroll
            for (int bq = 0; bq < BB; bq++) s_dbw[warp * BB + bq] = v[bq];
        __syncthreads();
        if (t == 0) {
            double a = 0.0;
#pragma unroll
            for (int bq = 0; bq < BB; bq++) {
                double s = 0.0;
#pragma unroll
                for (int wq = 0; wq < 8; wq++) s += s_dbw[wq * BB + bq];
                const double d = s / (double)LL - (double)CAP_F;
                a += d * d;
            }
            out[2 * BLT] = (float)((double)AUX_W * a / (double)BB);
        }
        return;
    }

    // ---------------- per-row top-CAP select ----------------
    const int srow = bid;
    unsigned k[SEPT];
    {
        const uint4* kr = reinterpret_cast<const uint4*>(g_keys + srow * LL);
#pragma unroll
        for (int q = 0; q < SEPT / 4; q++) {
            const uint4 v = __ldg(&kr[t * (SEPT / 4) + q]);
            k[q * 4 + 0] = v.x; k[q * 4 + 1] = v.y;
            k[q * 4 + 2] = v.z; k[q * 4 + 3] = v.w;
        }
    }

    // ---- pass 0: histogram prebuilt by matvec; read, then zero for replay
    const unsigned h0 = g_hist[srow][t];
    g_hist[srow][t] = 0u;              // reset for next graph replay
    if (t == 0) { s_cnt = 0u; s_eqn = 0; }
    {
        unsigned v = h0;
#pragma unroll
        for (int o = 1; o < 32; o <<= 1) {
            const unsigned u = __shfl_down_sync(0xffffffffu, v, o);
            if (lane + o < 32) v += u;
        }
        if (lane == 0) s_tot[warp] = v;
        __syncthreads();
        unsigned carry = 0;
#pragma unroll
        for (int w2 = 0; w2 < 8; w2++) if (w2 > warp) carry += s_tot[w2];
        const unsigned S = v + carry;                 // suffix incl. own bin
        if (h0 > 0u && S >= (unsigned)CAP && (S - h0) < (unsigned)CAP) {
            s_state[0] = (unsigned)t << 24;
            s_state[1] = (unsigned)CAP - (S - h0);
        }
        __syncthreads();
    }

    // ---- passes 1-3: prefix-filtered (few participants) ----
#pragma unroll
    for (int pass = 1; pass < 4; pass++) {
        const int s  = 24 - 8 * pass;
        const int hs = s + 8;
        s_hist[t] = 0u;
        __syncthreads();
        const unsigned prefix = s_state[0];
        const unsigned need   = s_state[1];
#pragma unroll
        for (int j = 0; j < SEPT; j++) {
            if (((k[j] ^ prefix) >> hs) == 0u)
                atomicAdd(&s_hist[(k[j] >> s) & 255u], 1u);
        }
        __syncthreads();
        const unsigned h = s_hist[t];
        unsigned v = h;
#pragma unroll
        for (int o = 1; o < 32; o <<= 1) {
            const unsigned u = __shfl_down_sync(0xffffffffu, v, o);
            if (lane + o < 32) v += u;
        }
        if (lane == 0) s_tot[warp] = v;
        __syncthreads();
        unsigned carry = 0;
#pragma unroll
        for (int w2 = 0; w2 < 8; w2++) if (w2 > warp) carry += s_tot[w2];
        const unsigned S = v + carry;
        if (h > 0u && S >= need && (S - h) < need) {
            s_state[0] = prefix | ((unsigned)t << s);
            s_state[1] = need - (S - h);
        }
        __syncthreads();
    }
    const unsigned thr = s_state[0];                  // exact CAP-th largest

    // mask write + strict-greater count + tie collection (from registers)
    float4* m4 = reinterpret_cast<float4*>(out + srow * LL);
    int cg = 0;
#pragma unroll
    for (int q = 0; q < SEPT / 4; q++) {
        float4 mv;
        mv.x = (k[q * 4 + 0] > thr) ? 1.0f : 0.0f;
        mv.y = (k[q * 4 + 1] > thr) ? 1.0f : 0.0f;
        mv.z = (k[q * 4 + 2] > thr) ? 1.0f : 0.0f;
        mv.w = (k[q * 4 + 3] > thr) ? 1.0f : 0.0f;
        m4[t * (SEPT / 4) + q] = mv;
        cg += (int)mv.x + (int)mv.y + (int)mv.z + (int)mv.w;
#pragma unroll
        for (int c = 0; c < 4; c++) {
            if (k[q * 4 + c] == thr) {
                const int p = atomicAdd(&s_eqn, 1);
                if (p < 256) s_eqi[p] = t * SEPT + q * 4 + c;
            }
        }
    }
    cg = __reduce_add_sync(0xffffffffu, cg);
    if (lane == 0 && cg) atomicAdd(&s_cnt, (unsigned)cg);
    __syncthreads();

    // promote lowest-index ties to fill exactly CAP (jax top_k order)
    if (t == 0) {
        float* m = out + srow * LL;
        int need = CAP - (int)s_cnt;
        const int n = (s_eqn < 256) ? s_eqn : 256;
        for (int sel = 0; sel < need; sel++) {
            int best = 0x7fffffff, bi = -1;
            for (int q = 0; q < n; q++)
                if (s_eqi[q] >= 0 && s_eqi[q] < best) { best = s_eqi[q]; bi = q; }
            if (bi < 0) break;
            m[best]   = 1.0f;
            s_eqi[bi] = -1;
        }
    }
}

// ---------------------------------------------------------------------------
extern "C" void kernel_launch(void* const* d_in, const int* in_sizes, int n_in,
                              void* d_out, int out_size)
{
    const float* x     = (const float*)d_in[0];
    const float* noise = (const float*)d_in[1];
    const float* w     = (const float*)d_in[2];
    float* out = (float*)d_out;   // [mask BL | logits BL | aux 1]
    (void)in_sizes; (void)n_in; (void)out_size;

    matvec_kernel<<<NBLK, TPB>>>(x, noise, w, out);

    // PDL secondary: prologue overlaps the matvec tail.
    cudaLaunchConfig_t cfg = {};
    cfg.gridDim  = dim3(BB + 1, 1, 1);
    cfg.blockDim = dim3(TPB, 1, 1);
    cfg.dynamicSmemBytes = 0;
    cfg.stream = 0;
    cudaLaunchAttribute attrs[1];
    attrs[0].id = cudaLaunchAttributeProgrammaticStreamSerialization;
    attrs[0].val.programmaticStreamSerializationAllowed = 1;
    cfg.attrs = attrs;
    cfg.numAttrs = 1;
    cudaLaunchKernelEx(&cfg, select_aux_kernel, out);
}